// round 9
// baseline (speedup 1.0000x reference)
#include <cuda_runtime.h>
#include <stdint.h>

// AddRadiusEdgeIndex: dense [N,N] float32 mask (1.0f/0.0f),
// mask[i,j] = (||p_i - p_j|| <= 3), reference-exact fp32 rounding (rel_err==0):
//   sq  = (x*x + y*y) + z*z ; dot = fmaf(z,z',fmaf(y,y',x*x')) ;
//   d2  = fmaf(-2, dot, sq_i + sq_j) ; mask = d2 <= 9
//
// R8 -> R9: limiter identified as the chip-wide LTS byte cap (~6300 B/cyc,
// path-independent): 268 MB output / ~6.6 TB/s = ~40.5 us floor, which all of
// R3..R8 sit on. This round trims the non-overlapped residue only: JPT 4->8
// (2 independent STG.128 per LDS broadcast, amortized loop overhead), IPB 8,
// plain stores (hints proved neutral). Packed f32x2 math retained.

#define NPTS 8192
#define JPT  8     // j-points per thread = 4 packed lanes, 2 float4 stores/row
#define TPB  256   // 2048 j-cols per block
#define IPB  8     // i-rows per block; grid = 4 * 1024 = 4096

typedef unsigned long long u64;

__device__ __forceinline__ u64 pack2(float lo, float hi)
{
    u64 r; asm("mov.b64 %0, {%1, %2};" : "=l"(r) : "f"(lo), "f"(hi)); return r;
}
__device__ __forceinline__ u64 mul2(u64 a, u64 b)
{
    u64 r; asm("mul.rn.f32x2 %0, %1, %2;" : "=l"(r) : "l"(a), "l"(b)); return r;
}
__device__ __forceinline__ u64 add2(u64 a, u64 b)
{
    u64 r; asm("add.rn.f32x2 %0, %1, %2;" : "=l"(r) : "l"(a), "l"(b)); return r;
}
__device__ __forceinline__ u64 fma2(u64 a, u64 b, u64 c)
{
    u64 r; asm("fma.rn.f32x2 %0, %1, %2, %3;" : "=l"(r) : "l"(a), "l"(b), "l"(c)); return r;
}
__device__ __forceinline__ float set_le9(float a)
{
    float r; asm("set.le.f32.f32 %0, %1, 0f41100000;" : "=f"(r) : "f"(a)); return r;
}

__global__ __launch_bounds__(TPB, 4)
void radius_mask_kernel(const float* __restrict__ pos, float4* __restrict__ out)
{
    __shared__ ulonglong2 si2[IPB][2];   // per i-row: {x,x|y,y}, {z,z|q,q}

    const int t  = threadIdx.x;
    const int jb = blockIdx.x & 3;           // j-block: 4 per row-stripe
    const int ib = blockIdx.x >> 2;          // i-stripe: 1024 of them
    const int i0 = ib * IPB;
    const int j0 = jb * (TPB * JPT) + t * JPT;

    if (t < IPB) {
        const int i = i0 + t;
        float x = pos[3 * i + 0];
        float y = pos[3 * i + 1];
        float z = pos[3 * i + 2];
        float q = __fadd_rn(__fadd_rn(__fmul_rn(x, x), __fmul_rn(y, y)),
                            __fmul_rn(z, z));
        si2[t][0] = make_ulonglong2(pack2(x, x), pack2(y, y));
        si2[t][1] = make_ulonglong2(pack2(z, z), pack2(q, q));
    }

    // 8 register-resident j-points as 4 packed lanes
    u64 xj2[4], yj2[4], zj2[4], sj2[4];
#pragma unroll
    for (int g = 0; g < 4; g++) {
        float xa = pos[3 * (j0 + 2 * g) + 0];
        float ya = pos[3 * (j0 + 2 * g) + 1];
        float za = pos[3 * (j0 + 2 * g) + 2];
        float xb = pos[3 * (j0 + 2 * g + 1) + 0];
        float yb = pos[3 * (j0 + 2 * g + 1) + 1];
        float zb = pos[3 * (j0 + 2 * g + 1) + 2];
        float qa = __fadd_rn(__fadd_rn(__fmul_rn(xa, xa), __fmul_rn(ya, ya)),
                             __fmul_rn(za, za));
        float qb = __fadd_rn(__fadd_rn(__fmul_rn(xb, xb), __fmul_rn(yb, yb)),
                             __fmul_rn(zb, zb));
        xj2[g] = pack2(xa, xb);
        yj2[g] = pack2(ya, yb);
        zj2[g] = pack2(za, zb);
        sj2[g] = pack2(qa, qb);
    }

    __syncthreads();

    const u64 NEG2 = 0xC0000000C0000000ull;   // {-2.0f, -2.0f}

    float4* dst = out + (size_t)i0 * (NPTS / 4) + (j0 >> 2);

#pragma unroll
    for (int ii = 0; ii < IPB; ii++) {
        const ulonglong2 A = si2[ii][0];      // LDS.128 broadcast
        const ulonglong2 B = si2[ii][1];

        float v[JPT];
#pragma unroll
        for (int g = 0; g < 4; g++) {
            u64 dot = fma2(zj2[g], B.x, fma2(yj2[g], A.y, mul2(xj2[g], A.x)));
            u64 d2  = fma2(NEG2, dot, add2(B.y, sj2[g]));
            float lo, hi;
            asm("mov.b64 {%0, %1}, %2;" : "=f"(lo), "=f"(hi) : "l"(d2));
            v[2 * g + 0] = set_le9(lo);
            v[2 * g + 1] = set_le9(hi);
        }
        dst[0] = make_float4(v[0], v[1], v[2], v[3]);
        dst[1] = make_float4(v[4], v[5], v[6], v[7]);
        dst += NPTS / 4;
    }
}

extern "C" void kernel_launch(void* const* d_in, const int* in_sizes, int n_in,
                              void* d_out, int out_size)
{
    const float* pos = (const float*)d_in[0];
    float4* out = (float4*)d_out;
    radius_mask_kernel<<<(NPTS / (TPB * JPT)) * (NPTS / IPB), TPB>>>(pos, out);
}

// round 10
// speedup vs baseline: 1.7631x; 1.7631x over previous
#include <cuda_runtime.h>
#include <stdint.h>

// AddRadiusEdgeIndex: dense [N,N] float32 mask (1.0f/0.0f),
// mask[i,j] = (||p_i - p_j|| <= 3), reference-exact fp32 rounding (rel_err==0):
//   sq  = (x*x + y*y) + z*z                       (plain rn mul/add)
//   dot = fmaf(z,z', fmaf(y,y', x*x'))            (gemm k-loop fma chain)
//   d2  = fmaf(-2, dot, sq_i + sq_j)              (2*dot exact)
//   mask = d2 <= 9
//
// R9 -> R10: revert to the R7 configuration — the measured optimum.
// Final model: the kernel sits on the chip-wide LTS byte-throughput cap
// (~6300 B/cyc, path-independent): 268 MB of output / ~6.6 TB/s ~= 40.5 us.
// Evidence: R3(STG scalar-sel), R4(FSET), R5(evict-first), R7(f32x2),
// R8(L2 policy split) all land 40.3-41.0 us with issue 26-41%, occ 57-67%,
// DRAM 62-65% -- nothing else binds. R6 (TMA drain) and R9 (non-contiguous
// stores) regressed by breaking the store path. Requirements for the floor:
//   - lane-contiguous 16 B/thread STG.128 (one fully-written 128B line per
//     4 lanes; R9 showed stride-32B stores double L1tex wavefronts)
//   - >=4 resident CTAs/SM to keep the store stream fed (R2 showed 1 CTA
//     starves it)
// Packed f32x2 math (PTX-only FFMA2/FADD2/FMUL2) keeps issue at 26% -- not
// needed for the floor but harmless and leaves headroom.

#define NPTS 8192
#define JPT  4     // j-points per thread (= 2 packed lanes), one STG.128/row
#define TPB  256   // 1024 j-cols per block
#define IPB  16    // i-rows per block; grid = 8 * 512 = 4096

typedef unsigned long long u64;

__device__ __forceinline__ u64 pack2(float lo, float hi)
{
    u64 r; asm("mov.b64 %0, {%1, %2};" : "=l"(r) : "f"(lo), "f"(hi)); return r;
}
__device__ __forceinline__ u64 mul2(u64 a, u64 b)
{
    u64 r; asm("mul.rn.f32x2 %0, %1, %2;" : "=l"(r) : "l"(a), "l"(b)); return r;
}
__device__ __forceinline__ u64 add2(u64 a, u64 b)
{
    u64 r; asm("add.rn.f32x2 %0, %1, %2;" : "=l"(r) : "l"(a), "l"(b)); return r;
}
__device__ __forceinline__ u64 fma2(u64 a, u64 b, u64 c)
{
    u64 r; asm("fma.rn.f32x2 %0, %1, %2, %3;" : "=l"(r) : "l"(a), "l"(b), "l"(c)); return r;
}
__device__ __forceinline__ float set_le9(float a)
{
    float r; asm("set.le.f32.f32 %0, %1, 0f41100000;" : "=f"(r) : "f"(a)); return r;
}

__global__ __launch_bounds__(TPB, 6)
void radius_mask_kernel(const float* __restrict__ pos, float4* __restrict__ out)
{
    // per i-row, pre-packed broadcasts: [0]={x,x | y,y}  [1]={z,z | q,q}
    __shared__ ulonglong2 si2[IPB][2];

    const int t  = threadIdx.x;
    const int jb = blockIdx.x & 7;          // j-block: 8 per row-stripe
    const int ib = blockIdx.x >> 3;         // i-stripe: 512 of them
    const int i0 = ib * IPB;
    const int j0 = jb * (TPB * JPT) + t * JPT;

    if (t < IPB) {
        const int i = i0 + t;
        float x = pos[3 * i + 0];
        float y = pos[3 * i + 1];
        float z = pos[3 * i + 2];
        float q = __fadd_rn(__fadd_rn(__fmul_rn(x, x), __fmul_rn(y, y)),
                            __fmul_rn(z, z));
        si2[t][0] = make_ulonglong2(pack2(x, x), pack2(y, y));
        si2[t][1] = make_ulonglong2(pack2(z, z), pack2(q, q));
    }

    // 4 register-resident j-points as 2 packed lanes
    u64 xj2[2], yj2[2], zj2[2], sj2[2];
#pragma unroll
    for (int g = 0; g < 2; g++) {
        float xa = pos[3 * (j0 + 2 * g) + 0];
        float ya = pos[3 * (j0 + 2 * g) + 1];
        float za = pos[3 * (j0 + 2 * g) + 2];
        float xb = pos[3 * (j0 + 2 * g + 1) + 0];
        float yb = pos[3 * (j0 + 2 * g + 1) + 1];
        float zb = pos[3 * (j0 + 2 * g + 1) + 2];
        float qa = __fadd_rn(__fadd_rn(__fmul_rn(xa, xa), __fmul_rn(ya, ya)),
                             __fmul_rn(za, za));
        float qb = __fadd_rn(__fadd_rn(__fmul_rn(xb, xb), __fmul_rn(yb, yb)),
                             __fmul_rn(zb, zb));
        xj2[g] = pack2(xa, xb);
        yj2[g] = pack2(ya, yb);
        zj2[g] = pack2(za, zb);
        sj2[g] = pack2(qa, qb);
    }

    __syncthreads();

    const u64 NEG2 = 0xC0000000C0000000ull;   // {-2.0f, -2.0f}

    float4* dst = out + (size_t)i0 * (NPTS / 4) + (j0 >> 2);

#pragma unroll 8
    for (int ii = 0; ii < IPB; ii++) {
        const ulonglong2 A = si2[ii][0];      // {xx, yy}  LDS.128 broadcast
        const ulonglong2 B = si2[ii][1];      // {zz, qq}

        float v[JPT];
#pragma unroll
        for (int g = 0; g < 2; g++) {
            u64 dot = fma2(zj2[g], B.x, fma2(yj2[g], A.y, mul2(xj2[g], A.x)));
            u64 d2  = fma2(NEG2, dot, add2(B.y, sj2[g]));
            float lo, hi;
            asm("mov.b64 {%0, %1}, %2;" : "=f"(lo), "=f"(hi) : "l"(d2));
            v[2 * g + 0] = set_le9(lo);
            v[2 * g + 1] = set_le9(hi);
        }
        *dst = make_float4(v[0], v[1], v[2], v[3]);
        dst += NPTS / 4;
    }
}

extern "C" void kernel_launch(void* const* d_in, const int* in_sizes, int n_in,
                              void* d_out, int out_size)
{
    const float* pos = (const float*)d_in[0];
    float4* out = (float4*)d_out;
    radius_mask_kernel<<<(NPTS / (TPB * JPT)) * (NPTS / IPB), TPB>>>(pos, out);
}